// round 16
// baseline (speedup 1.0000x reference)
#include <cuda_runtime.h>
#include <cuda_fp16.h>
#include <cstdint>
#include <math.h>

// ---------------------------------------------------------------------------
// Problem constants
// ---------------------------------------------------------------------------
#define BATCH 4
#define SEQ   4096
#define HID   1024
#define NH    16
#define DH    64
#define M_TOT (BATCH * SEQ)   // 16384
#define N_TOT (3 * HID)       // 3072
#define K_TOT HID             // 1024

// Scratch (device globals: allocation-free rule)
__device__ __half g_qkv[(size_t)M_TOT * N_TOT];  // 96 MB
__device__ __half g_ah[(size_t)M_TOT * K_TOT];   // 32 MB
__device__ __half g_wh[(size_t)N_TOT * K_TOT];   // 6 MB
__device__ unsigned int g_cnt[M_TOT / 128];      // GEMM-done counters (self-reset)
__device__ unsigned int g_done[M_TOT / 128];     // attn-done counters (self-reset)

// ---------------------------------------------------------------------------
// Helpers (sm_80-era PTX only)
// ---------------------------------------------------------------------------
__device__ __forceinline__ uint32_t smem_u32(const void* p) {
    uint32_t a;
    asm("{ .reg .u64 t; cvta.to.shared.u64 t, %1; cvt.u32.u64 %0, t; }"
        : "=r"(a) : "l"(p));
    return a;
}

__device__ __forceinline__ void cp_async16(uint32_t s, const void* g) {
    asm volatile("cp.async.cg.shared.global [%0], [%1], 16;" :: "r"(s), "l"(g) : "memory");
}

__device__ __forceinline__ void ldsm_x4(uint32_t& r0, uint32_t& r1,
                                        uint32_t& r2, uint32_t& r3, uint32_t addr) {
    asm volatile("ldmatrix.sync.aligned.m8n8.x4.shared.b16 {%0,%1,%2,%3}, [%4];"
                 : "=r"(r0), "=r"(r1), "=r"(r2), "=r"(r3) : "r"(addr));
}

__device__ __forceinline__ void mma_fp16(float* c, const uint32_t* a,
                                         uint32_t b0, uint32_t b1) {
    asm volatile(
        "mma.sync.aligned.m16n8k16.row.col.f32.f16.f16.f32 "
        "{%0,%1,%2,%3}, {%4,%5,%6,%7}, {%8,%9}, {%0,%1,%2,%3};"
        : "+f"(c[0]), "+f"(c[1]), "+f"(c[2]), "+f"(c[3])
        : "r"(a[0]), "r"(a[1]), "r"(a[2]), "r"(a[3]), "r"(b0), "r"(b1));
}

// ---------------------------------------------------------------------------
// Conversion: A(fp32) -> fp16, W(fp32) -> fp16
// ---------------------------------------------------------------------------
#define N4_A ((size_t)M_TOT * K_TOT / 4)
#define N4_W ((size_t)N_TOT * K_TOT / 4)
#define N4_TOTAL (N4_A + N4_W)

__global__ __launch_bounds__(256) void convert_kernel(
    const float* __restrict__ A, const float* __restrict__ W)
{
    size_t idx = (size_t)blockIdx.x * blockDim.x + threadIdx.x;
    if (idx >= N4_TOTAL) return;

    if (idx < N4_A) {
        float4 v = ((const float4*)A)[idx];
        __half h[4] = { __float2half_rn(v.x), __float2half_rn(v.y),
                        __float2half_rn(v.z), __float2half_rn(v.w) };
        *(uint2*)(g_ah + idx * 4) = *(uint2*)h;
    } else {
        size_t j = idx - N4_A;
        float4 v = ((const float4*)W)[j];
        __half h[4] = { __float2half_rn(v.x), __float2half_rn(v.y),
                        __float2half_rn(v.z), __float2half_rn(v.w) };
        *(uint2*)(g_wh + j * 4) = *(uint2*)h;
    }
}

// ---------------------------------------------------------------------------
// Fused GEMM + all-CTA-sliced attention.
// GEMM (R12 form, bitwise-identical): CTA 128x128, 4 warps of 64x64, BK=64,
// 3 stages, 2 CTAs/SM. After epilogue: release-increment g_cnt[m-block],
// spin-wait (acquire + nanosleep) for 24, then each CTA runs attention for
// positions p = m0 + blockIdx.x + 24*i (its 1/24 slice; 5-6 positions),
// warp-per-position (R15 body), reusing GEMM smem.
// ---------------------------------------------------------------------------
#define BK      64
#define KITERS  (K_TOT / BK)     // 16
#define STAGES  3
#define ROWB    144
#define TILEB   (128 * ROWB)     // 18432
#define STAGEB  (2 * TILEB)      // 36864
#define GEMM_SMEM (STAGES * STAGEB)  // 110592
#define AWARP_SMEM 8000              // per-warp attn scratch (4*8000 < GEMM_SMEM)

__global__ void __launch_bounds__(128, 2) gemm_attn_fused(
    const __half* __restrict__ Ah, const __half* __restrict__ Wh,
    const float* __restrict__ bias, __half* __restrict__ C,
    const float* __restrict__ mask, float* __restrict__ out)
{
    extern __shared__ char smem[];
    const uint32_t sb = smem_u32(smem);
    const int t    = threadIdx.x;
    const int wid  = t >> 5;
    const int lane = t & 31;
    const int m0 = blockIdx.y * 128;
    const int n0 = blockIdx.x * 128;
    const int wm = (wid & 1) * 64;
    const int wn = (wid >> 1) * 64;

    // ======================= GEMM phase (R12, unchanged) =======================
    {
        const char* aptr = (const char*)(Ah + (size_t)(m0 + (t >> 3)) * K_TOT) + (t & 7) * 16;
        const char* wptr = (const char*)(Wh + (size_t)(n0 + (t >> 3)) * K_TOT) + (t & 7) * 16;
        const uint32_t so0 = (uint32_t)((t >> 3) * ROWB + (t & 7) * 16);

        auto load_stage = [&](int s) {
            const uint32_t dst = sb + (s % STAGES) * STAGEB + so0;
            const int koff = s * (BK * 2);
#pragma unroll
            for (int i = 0; i < 8; i++) {
                cp_async16(dst + (uint32_t)(i * 16 * ROWB),
                           aptr + (size_t)i * 16 * K_TOT * 2 + koff);
                cp_async16(dst + TILEB + (uint32_t)(i * 16 * ROWB),
                           wptr + (size_t)i * 16 * K_TOT * 2 + koff);
            }
        };

        float acc[4][8][4];
#pragma unroll
        for (int mt = 0; mt < 4; mt++)
#pragma unroll
            for (int nt = 0; nt < 8; nt++)
#pragma unroll
                for (int q = 0; q < 4; q++) acc[mt][nt][q] = 0.0f;

#pragma unroll
        for (int s = 0; s < STAGES - 1; s++) {
            load_stage(s);
            asm volatile("cp.async.commit_group;" ::: "memory");
        }

        const int lrow  = lane & 15;
        const int lkoff = (lane >> 4) * 16;

        for (int kit = 0; kit < KITERS; kit++) {
            asm volatile("cp.async.wait_group %0;" :: "n"(STAGES - 2) : "memory");
            __syncthreads();

            if (kit + STAGES - 1 < KITERS) load_stage(kit + STAGES - 1);
            asm volatile("cp.async.commit_group;" ::: "memory");

            const uint32_t bufb = sb + (kit % STAGES) * STAGEB;
            const uint32_t aH = bufb;
            const uint32_t wH = bufb + TILEB;

#pragma unroll
            for (int ks = 0; ks < 4; ks++) {
                const uint32_t kb = (uint32_t)(ks * 32 + lkoff);

                uint32_t af[4][4];
#pragma unroll
                for (int mt = 0; mt < 4; mt++) {
                    const uint32_t ro = (uint32_t)((wm + mt * 16 + lrow) * ROWB) + kb;
                    ldsm_x4(af[mt][0], af[mt][1], af[mt][2], af[mt][3], aH + ro);
                }

                uint32_t bh0[8], bh1[8];
#pragma unroll
                for (int np = 0; np < 4; np++) {
                    const uint32_t ro = (uint32_t)((wn + np * 16 + lrow) * ROWB) + kb;
                    uint32_t r0, r1, r2, r3;
                    ldsm_x4(r0, r1, r2, r3, wH + ro);
                    bh0[np * 2] = r0; bh1[np * 2] = r2;
                    bh0[np * 2 + 1] = r1; bh1[np * 2 + 1] = r3;
                }

#pragma unroll
                for (int mt = 0; mt < 4; mt++)
#pragma unroll
                    for (int nt = 0; nt < 8; nt++)
                        mma_fp16(acc[mt][nt], af[mt], bh0[nt], bh1[nt]);
            }
        }

#pragma unroll
        for (int mt = 0; mt < 4; mt++) {
            const int r = m0 + wm + mt * 16 + (lane >> 2);
#pragma unroll
            for (int nt = 0; nt < 8; nt++) {
                const int cc = n0 + wn + nt * 8 + (lane & 3) * 2;
                const float bx = __ldg(bias + cc);
                const float by = __ldg(bias + cc + 1);
                __half2 h0, h1;
                h0.x = __float2half_rn(acc[mt][nt][0] + bx);
                h0.y = __float2half_rn(acc[mt][nt][1] + by);
                h1.x = __float2half_rn(acc[mt][nt][2] + bx);
                h1.y = __float2half_rn(acc[mt][nt][3] + by);
                *(__half2*)(C + (size_t)r * N_TOT + cc)       = h0;
                *(__half2*)(C + (size_t)(r + 8) * N_TOT + cc) = h1;
            }
        }
    }

    // ============ m-block barrier: release-increment + acquire spin ============
    __syncthreads();
    __threadfence();                       // publish this CTA's qkv stores
    if (t == 0) {
        atomicAdd(&g_cnt[blockIdx.y], 1u);
        unsigned int c;
        do {
            asm volatile("ld.global.acquire.gpu.u32 %0, [%1];"
                         : "=r"(c) : "l"(&g_cnt[blockIdx.y]) : "memory");
            if (c < 24u) __nanosleep(200);
        } while (c < 24u);
    }
    __syncthreads();                       // all threads see spin result; smem reuse safe

    // ======================= attention phase (R15 body) =======================
    __half* sqkv = (__half*)(smem + wid * AWARP_SMEM);
    float*  sw   = (float*)(smem + wid * AWARP_SMEM + 6912);
    const int jn = blockIdx.x;             // 0..23 slice index
    const int h  = lane >> 1;
    const int gh = lane & 1;

    for (int i = wid; jn + 24 * i < 128; i += 4) {
        const int p = m0 + jn + 24 * i;

        {
            const uint4* src = (const uint4*)(C + (size_t)p * N_TOT);
#pragma unroll
            for (int q = lane; q < 384; q += 32) {
                uint4 raw = src[q];
                const int e = q * 8;
                const int arr = e >> 10;
                const int r   = e & 1023;
                *(uint4*)(sqkv + arr * 1152 + (r >> 6) * 72 + (r & 63)) = raw;
            }
        }
        __syncwarp();

        float s[8];
#pragma unroll
        for (int gi = 0; gi < 8; gi++) s[gi] = 0.0f;

        const __half* qrow = sqkv + h * 72;
#pragma unroll
        for (int d8 = 0; d8 < 8; d8++) {
            uint4 qraw = *(const uint4*)(qrow + d8 * 8);
            const __half2* qh2 = (const __half2*)&qraw;
            float qf[8];
#pragma unroll
            for (int j = 0; j < 4; j++) {
                float2 f = __half22float2(qh2[j]);
                qf[2 * j] = f.x; qf[2 * j + 1] = f.y;
            }
#pragma unroll
            for (int gi = 0; gi < 8; gi++) {
                const __half* krow = sqkv + 1152 + (gh * 8 + gi) * 72;
                uint4 kraw = *(const uint4*)(krow + d8 * 8);
                const __half2* kh2 = (const __half2*)&kraw;
#pragma unroll
                for (int j = 0; j < 4; j++) {
                    float2 f = __half22float2(kh2[j]);
                    s[gi] += qf[2 * j] * f.x + qf[2 * j + 1] * f.y;
                }
            }
        }

        {
            const float* mrow = mask + (size_t)p * (NH * NH) + h * NH + gh * 8;
            float4 m0v = *(const float4*)mrow;
            float4 m1v = *(const float4*)(mrow + 4);
            s[0] = s[0] * 0.125f + m0v.x; s[1] = s[1] * 0.125f + m0v.y;
            s[2] = s[2] * 0.125f + m0v.z; s[3] = s[3] * 0.125f + m0v.w;
            s[4] = s[4] * 0.125f + m1v.x; s[5] = s[5] * 0.125f + m1v.y;
            s[6] = s[6] * 0.125f + m1v.z; s[7] = s[7] * 0.125f + m1v.w;
        }

        float mx = s[0];
#pragma unroll
        for (int gi = 1; gi < 8; gi++) mx = fmaxf(mx, s[gi]);
        mx = fmaxf(mx, __shfl_xor_sync(0xffffffff, mx, 1));

        float sum = 0.0f;
#pragma unroll
        for (int gi = 0; gi < 8; gi++) { s[gi] = __expf(s[gi] - mx); sum += s[gi]; }
        sum += __shfl_xor_sync(0xffffffff, sum, 1);
        const float inv = 1.0f / sum;

#pragma unroll
        for (int gi = 0; gi < 8; gi++) sw[h * 17 + gh * 8 + gi] = s[gi] * inv;
        __syncwarp();

        float* orow = out + (size_t)p * HID + h * DH + gh * 32;
#pragma unroll
        for (int dhf = 0; dhf < 2; dhf++) {
            float acc2[16];
#pragma unroll
            for (int d = 0; d < 16; d++) acc2[d] = 0.0f;

#pragma unroll
            for (int g = 0; g < 16; g++) {
                const float wv = sw[h * 17 + g];
                const __half* vrow = sqkv + 2304 + g * 72 + gh * 32 + dhf * 16;
#pragma unroll
                for (int d8 = 0; d8 < 2; d8++) {
                    uint4 vr = *(const uint4*)(vrow + d8 * 8);
                    const __half2* vh2 = (const __half2*)&vr;
#pragma unroll
                    for (int j = 0; j < 4; j++) {
                        float2 f = __half22float2(vh2[j]);
                        acc2[d8 * 8 + 2 * j]     += wv * f.x;
                        acc2[d8 * 8 + 2 * j + 1] += wv * f.y;
                    }
                }
            }

#pragma unroll
            for (int d4 = 0; d4 < 4; d4++) {
                float4 o;
                o.x = acc2[4 * d4]; o.y = acc2[4 * d4 + 1];
                o.z = acc2[4 * d4 + 2]; o.w = acc2[4 * d4 + 3];
                *(float4*)(orow + dhf * 16 + 4 * d4) = o;
            }
        }
        __syncwarp();   // before next iteration overwrites sqkv/sw
    }

    // ============ per-replay counter reset (last attn-finisher) ============
    __syncthreads();
    if (t == 0) {
        __threadfence();
        unsigned int old = atomicAdd(&g_done[blockIdx.y], 1u);
        if (old == 23u) {
            atomicExch(&g_cnt[blockIdx.y], 0u);
            atomicExch(&g_done[blockIdx.y], 0u);
        }
    }
}

// ---------------------------------------------------------------------------
// Launch — inputs: 0=query, 1=key, 2=value, 3=attn_mask, 4=W_qkv, 5=b_qkv
// ---------------------------------------------------------------------------
extern "C" void kernel_launch(void* const* d_in, const int* in_sizes, int n_in,
                              void* d_out, int out_size)
{
    const float* query = (const float*)d_in[0];
    const float* mask  = (const float*)d_in[3];
    const float* W     = (const float*)d_in[4];
    const float* bias  = (const float*)d_in[5];
    float* out = (float*)d_out;

    __half *qkv, *ah, *wh;
    cudaGetSymbolAddress((void**)&qkv, g_qkv);
    cudaGetSymbolAddress((void**)&ah, g_ah);
    cudaGetSymbolAddress((void**)&wh, g_wh);

    const int cvt_blocks = (int)((N4_TOTAL + 255) / 256);
    convert_kernel<<<cvt_blocks, 256>>>(query, W);

    cudaFuncSetAttribute(gemm_attn_fused, cudaFuncAttributeMaxDynamicSharedMemorySize,
                         GEMM_SMEM);
    dim3 ggrid(N_TOT / 128, M_TOT / 128);  // (24, 128)
    gemm_attn_fused<<<ggrid, 128, GEMM_SMEM>>>(ah, wh, bias, qkv, mask, out);
}

// round 17
// speedup vs baseline: 1.1297x; 1.1297x over previous
#include <cuda_runtime.h>
#include <cuda_fp16.h>
#include <cstdint>
#include <math.h>

// ---------------------------------------------------------------------------
// Problem constants
// ---------------------------------------------------------------------------
#define BATCH 4
#define SEQ   4096
#define HID   1024
#define NH    16
#define DH    64
#define M_TOT (BATCH * SEQ)   // 16384
#define N_TOT (3 * HID)       // 3072
#define K_TOT HID             // 1024

// Scratch (device globals: allocation-free rule)
__device__ __half g_qkv[(size_t)M_TOT * N_TOT];  // 96 MB
__device__ __half g_ah[(size_t)M_TOT * K_TOT];   // 32 MB
__device__ __half g_wh[(size_t)N_TOT * K_TOT];   // 6 MB

// ---------------------------------------------------------------------------
// Helpers (sm_80-era PTX only)
// ---------------------------------------------------------------------------
__device__ __forceinline__ uint32_t smem_u32(const void* p) {
    uint32_t a;
    asm("{ .reg .u64 t; cvta.to.shared.u64 t, %1; cvt.u32.u64 %0, t; }"
        : "=r"(a) : "l"(p));
    return a;
}

__device__ __forceinline__ void cp_async16(uint32_t s, const void* g) {
    asm volatile("cp.async.cg.shared.global [%0], [%1], 16;" :: "r"(s), "l"(g) : "memory");
}

__device__ __forceinline__ void ldsm_x4(uint32_t& r0, uint32_t& r1,
                                        uint32_t& r2, uint32_t& r3, uint32_t addr) {
    asm volatile("ldmatrix.sync.aligned.m8n8.x4.shared.b16 {%0,%1,%2,%3}, [%4];"
                 : "=r"(r0), "=r"(r1), "=r"(r2), "=r"(r3) : "r"(addr));
}

__device__ __forceinline__ void mma_fp16(float* c, const uint32_t* a,
                                         uint32_t b0, uint32_t b1) {
    asm volatile(
        "mma.sync.aligned.m16n8k16.row.col.f32.f16.f16.f32 "
        "{%0,%1,%2,%3}, {%4,%5,%6,%7}, {%8,%9}, {%0,%1,%2,%3};"
        : "+f"(c[0]), "+f"(c[1]), "+f"(c[2]), "+f"(c[3])
        : "r"(a[0]), "r"(a[1]), "r"(a[2]), "r"(a[3]), "r"(b0), "r"(b1));
}

// ---------------------------------------------------------------------------
// Conversion: A(fp32) -> fp16, W(fp32) -> fp16
// ---------------------------------------------------------------------------
#define N4_A ((size_t)M_TOT * K_TOT / 4)
#define N4_W ((size_t)N_TOT * K_TOT / 4)
#define N4_TOTAL (N4_A + N4_W)

__global__ __launch_bounds__(256) void convert_kernel(
    const float* __restrict__ A, const float* __restrict__ W)
{
    size_t idx = (size_t)blockIdx.x * blockDim.x + threadIdx.x;
    if (idx >= N4_TOTAL) return;

    if (idx < N4_A) {
        float4 v = ((const float4*)A)[idx];
        __half h[4] = { __float2half_rn(v.x), __float2half_rn(v.y),
                        __float2half_rn(v.z), __float2half_rn(v.w) };
        *(uint2*)(g_ah + idx * 4) = *(uint2*)h;
    } else {
        size_t j = idx - N4_A;
        float4 v = ((const float4*)W)[j];
        __half h[4] = { __float2half_rn(v.x), __float2half_rn(v.y),
                        __float2half_rn(v.z), __float2half_rn(v.w) };
        *(uint2*)(g_wh + j * 4) = *(uint2*)h;
    }
}

// ---------------------------------------------------------------------------
// GEMM fp16 (R12 form — at the legacy-HMMA hardware rate; unchanged):
// CTA 128x128, 4 warps of 64x64, BK=64, 3 stages, 2 CTAs/SM.
// ---------------------------------------------------------------------------
#define BK      64
#define KITERS  (K_TOT / BK)     // 16
#define STAGES  3
#define ROWB    144
#define TILEB   (128 * ROWB)     // 18432
#define STAGEB  (2 * TILEB)      // 36864
#define GEMM_SMEM (STAGES * STAGEB)  // 110592

__global__ void __launch_bounds__(128, 2) gemm_qkv_mma(
    const __half* __restrict__ Ah, const __half* __restrict__ Wh,
    const float* __restrict__ bias, __half* __restrict__ C)
{
    extern __shared__ char smem[];
    const uint32_t sb = smem_u32(smem);
    const int t    = threadIdx.x;
    const int wid  = t >> 5;
    const int lane = t & 31;
    const int m0 = blockIdx.y * 128;
    const int n0 = blockIdx.x * 128;
    const int wm = (wid & 1) * 64;
    const int wn = (wid >> 1) * 64;

    const char* aptr = (const char*)(Ah + (size_t)(m0 + (t >> 3)) * K_TOT) + (t & 7) * 16;
    const char* wptr = (const char*)(Wh + (size_t)(n0 + (t >> 3)) * K_TOT) + (t & 7) * 16;
    const uint32_t so0 = (uint32_t)((t >> 3) * ROWB + (t & 7) * 16);

    auto load_stage = [&](int s) {
        const uint32_t dst = sb + (s % STAGES) * STAGEB + so0;
        const int koff = s * (BK * 2);
#pragma unroll
        for (int i = 0; i < 8; i++) {
            cp_async16(dst + (uint32_t)(i * 16 * ROWB),
                       aptr + (size_t)i * 16 * K_TOT * 2 + koff);
            cp_async16(dst + TILEB + (uint32_t)(i * 16 * ROWB),
                       wptr + (size_t)i * 16 * K_TOT * 2 + koff);
        }
    };

    float acc[4][8][4];
#pragma unroll
    for (int mt = 0; mt < 4; mt++)
#pragma unroll
        for (int nt = 0; nt < 8; nt++)
#pragma unroll
            for (int q = 0; q < 4; q++) acc[mt][nt][q] = 0.0f;

#pragma unroll
    for (int s = 0; s < STAGES - 1; s++) {
        load_stage(s);
        asm volatile("cp.async.commit_group;" ::: "memory");
    }

    const int lrow  = lane & 15;
    const int lkoff = (lane >> 4) * 16;

    for (int kit = 0; kit < KITERS; kit++) {
        asm volatile("cp.async.wait_group %0;" :: "n"(STAGES - 2) : "memory");
        __syncthreads();

        if (kit + STAGES - 1 < KITERS) load_stage(kit + STAGES - 1);
        asm volatile("cp.async.commit_group;" ::: "memory");

        const uint32_t bufb = sb + (kit % STAGES) * STAGEB;
        const uint32_t aH = bufb;
        const uint32_t wH = bufb + TILEB;

#pragma unroll
        for (int ks = 0; ks < 4; ks++) {
            const uint32_t kb = (uint32_t)(ks * 32 + lkoff);

            uint32_t af[4][4];
#pragma unroll
            for (int mt = 0; mt < 4; mt++) {
                const uint32_t ro = (uint32_t)((wm + mt * 16 + lrow) * ROWB) + kb;
                ldsm_x4(af[mt][0], af[mt][1], af[mt][2], af[mt][3], aH + ro);
            }

            uint32_t bh0[8], bh1[8];
#pragma unroll
            for (int np = 0; np < 4; np++) {
                const uint32_t ro = (uint32_t)((wn + np * 16 + lrow) * ROWB) + kb;
                uint32_t r0, r1, r2, r3;
                ldsm_x4(r0, r1, r2, r3, wH + ro);
                bh0[np * 2] = r0; bh1[np * 2] = r2;
                bh0[np * 2 + 1] = r1; bh1[np * 2 + 1] = r3;
            }

#pragma unroll
            for (int mt = 0; mt < 4; mt++)
#pragma unroll
                for (int nt = 0; nt < 8; nt++)
                    mma_fp16(acc[mt][nt], af[mt], bh0[nt], bh1[nt]);
        }
    }

#pragma unroll
    for (int mt = 0; mt < 4; mt++) {
        const int r = m0 + wm + mt * 16 + (lane >> 2);
#pragma unroll
        for (int nt = 0; nt < 8; nt++) {
            const int cc = n0 + wn + nt * 8 + (lane & 3) * 2;
            const float bx = __ldg(bias + cc);
            const float by = __ldg(bias + cc + 1);
            __half2 h0, h1;
            h0.x = __float2half_rn(acc[mt][nt][0] + bx);
            h0.y = __float2half_rn(acc[mt][nt][1] + by);
            h1.x = __float2half_rn(acc[mt][nt][2] + bx);
            h1.y = __float2half_rn(acc[mt][nt][3] + by);
            *(__half2*)(C + (size_t)r * N_TOT + cc)       = h0;
            *(__half2*)(C + (size_t)(r + 8) * N_TOT + cc) = h1;
        }
    }
}

// ---------------------------------------------------------------------------
// Attention v6: warp handles 4 positions SEQUENTIALLY with a double-buffered
// cp.async pipeline: issue load(i+1) -> wait load(i) -> compute(i).
// 3 of 4 qkv fills hidden under compute. Per-position math = R15 (identical
// numerics). Smem: 4 warps x (2 x 3456 halfs + 272 floats) = 59648 B/block.
// ---------------------------------------------------------------------------
#define POSW 4   // positions per warp

__global__ __launch_bounds__(128) void attn_kernel(
    const __half* __restrict__ qkv, const float* __restrict__ mask,
    float* __restrict__ out)
{
    __shared__ __align__(16) __half buf[4][2][3456];
    __shared__ __align__(16) float  swarr[4][272];   // [16][17]

    const int wid  = threadIdx.x >> 5;
    const int lane = threadIdx.x & 31;
    const int p0 = blockIdx.x * (4 * POSW) + wid * POSW;

    float* sw = swarr[wid];
    const int h  = lane >> 1;
    const int gh = lane & 1;

    auto issue_load = [&](int i, int b) {
        const char* src = (const char*)(qkv + (size_t)(p0 + i) * N_TOT);
        const uint32_t base = smem_u32(&buf[wid][b][0]);
#pragma unroll
        for (int q = lane; q < 384; q += 32) {
            const int e   = q * 8;
            const int arr = e >> 10;
            const int r   = e & 1023;
            cp_async16(base + (uint32_t)(arr * 2304 + (r >> 6) * 144 + (r & 63) * 2),
                       src + q * 16);
        }
        asm volatile("cp.async.commit_group;" ::: "memory");
    };

    issue_load(0, 0);

    for (int i = 0; i < POSW; i++) {
        if (i + 1 < POSW) {
            issue_load(i + 1, (i + 1) & 1);
            asm volatile("cp.async.wait_group 1;" ::: "memory");
        } else {
            asm volatile("cp.async.wait_group 0;" ::: "memory");
        }
        __syncwarp();

        const int p = p0 + i;
        const __half* sqkv = &buf[wid][i & 1][0];

        // ---- QK: 8 dot products of length 64 ----
        float s[8];
#pragma unroll
        for (int gi = 0; gi < 8; gi++) s[gi] = 0.0f;

        const __half* qrow = sqkv + h * 72;
#pragma unroll
        for (int d8 = 0; d8 < 8; d8++) {
            uint4 qraw = *(const uint4*)(qrow + d8 * 8);
            const __half2* qh2 = (const __half2*)&qraw;
            float qf[8];
#pragma unroll
            for (int j = 0; j < 4; j++) {
                float2 f = __half22float2(qh2[j]);
                qf[2 * j] = f.x; qf[2 * j + 1] = f.y;
            }
#pragma unroll
            for (int gi = 0; gi < 8; gi++) {
                const __half* krow = sqkv + 1152 + (gh * 8 + gi) * 72;
                uint4 kraw = *(const uint4*)(krow + d8 * 8);
                const __half2* kh2 = (const __half2*)&kraw;
#pragma unroll
                for (int j = 0; j < 4; j++) {
                    float2 f = __half22float2(kh2[j]);
                    s[gi] += qf[2 * j] * f.x + qf[2 * j + 1] * f.y;
                }
            }
        }

        // scale + mask
        {
            const float* mrow = mask + (size_t)p * (NH * NH) + h * NH + gh * 8;
            float4 m0v = *(const float4*)mrow;
            float4 m1v = *(const float4*)(mrow + 4);
            s[0] = s[0] * 0.125f + m0v.x; s[1] = s[1] * 0.125f + m0v.y;
            s[2] = s[2] * 0.125f + m0v.z; s[3] = s[3] * 0.125f + m0v.w;
            s[4] = s[4] * 0.125f + m1v.x; s[5] = s[5] * 0.125f + m1v.y;
            s[6] = s[6] * 0.125f + m1v.z; s[7] = s[7] * 0.125f + m1v.w;
        }

        // ---- softmax ----
        float mx = s[0];
#pragma unroll
        for (int gi = 1; gi < 8; gi++) mx = fmaxf(mx, s[gi]);
        mx = fmaxf(mx, __shfl_xor_sync(0xffffffff, mx, 1));

        float sum = 0.0f;
#pragma unroll
        for (int gi = 0; gi < 8; gi++) { s[gi] = __expf(s[gi] - mx); sum += s[gi]; }
        sum += __shfl_xor_sync(0xffffffff, sum, 1);
        const float inv = 1.0f / sum;

#pragma unroll
        for (int gi = 0; gi < 8; gi++) sw[h * 17 + gh * 8 + gi] = s[gi] * inv;
        __syncwarp();

        // ---- PV in two d-halves of 16 ----
        float* orow = out + (size_t)p * HID + h * DH + gh * 32;
#pragma unroll
        for (int dhf = 0; dhf < 2; dhf++) {
            float acc[16];
#pragma unroll
            for (int d = 0; d < 16; d++) acc[d] = 0.0f;

#pragma unroll
            for (int g = 0; g < 16; g++) {
                const float wv = sw[h * 17 + g];
                const __half* vrow = sqkv + 2304 + g * 72 + gh * 32 + dhf * 16;
#pragma unroll
                for (int d8 = 0; d8 < 2; d8++) {
                    uint4 vr = *(const uint4*)(vrow + d8 * 8);
                    const __half2* vh2 = (const __half2*)&vr;
#pragma unroll
                    for (int j = 0; j < 4; j++) {
                        float2 f = __half22float2(vh2[j]);
                        acc[d8 * 8 + 2 * j]     += wv * f.x;
                        acc[d8 * 8 + 2 * j + 1] += wv * f.y;
                    }
                }
            }

#pragma unroll
            for (int d4 = 0; d4 < 4; d4++) {
                float4 o;
                o.x = acc[4 * d4]; o.y = acc[4 * d4 + 1];
                o.z = acc[4 * d4 + 2]; o.w = acc[4 * d4 + 3];
                *(float4*)(orow + dhf * 16 + 4 * d4) = o;
            }
        }
        __syncwarp();   // all lanes done reading buf/sw before next overwrite
    }
}

// ---------------------------------------------------------------------------
// Launch — inputs: 0=query, 1=key, 2=value, 3=attn_mask, 4=W_qkv, 5=b_qkv
// ---------------------------------------------------------------------------
extern "C" void kernel_launch(void* const* d_in, const int* in_sizes, int n_in,
                              void* d_out, int out_size)
{
    const float* query = (const float*)d_in[0];
    const float* mask  = (const float*)d_in[3];
    const float* W     = (const float*)d_in[4];
    const float* bias  = (const float*)d_in[5];
    float* out = (float*)d_out;

    __half *qkv, *ah, *wh;
    cudaGetSymbolAddress((void**)&qkv, g_qkv);
    cudaGetSymbolAddress((void**)&ah, g_ah);
    cudaGetSymbolAddress((void**)&wh, g_wh);

    const int cvt_blocks = (int)((N4_TOTAL + 255) / 256);
    convert_kernel<<<cvt_blocks, 256>>>(query, W);

    cudaFuncSetAttribute(gemm_qkv_mma, cudaFuncAttributeMaxDynamicSharedMemorySize,
                         GEMM_SMEM);
    dim3 ggrid(N_TOT / 128, M_TOT / 128);  // (24, 128)
    gemm_qkv_mma<<<ggrid, 128, GEMM_SMEM>>>(ah, wh, bias, qkv);

    attn_kernel<<<M_TOT / (4 * POSW), 128>>>(qkv, mask, out);
}